// round 6
// baseline (speedup 1.0000x reference)
#include <cuda_runtime.h>
#include <cuda_bf16.h>
#include <math_constants.h>

// Shapes
#define B_  16
#define L_  4096
#define D_  1024

// Scratch (allocation-free rule: __device__ globals)
__device__ float g_decfeat[B_ * D_];   // dec_hidden @ W^T + b
__device__ float g_score[B_ * L_];     // pre-softmax scores

__device__ __forceinline__ float tanh_approx(float x) {
    float y;
    asm("tanh.approx.f32 %0, %1;" : "=f"(y) : "f"(x));
    return y;
}

__device__ __forceinline__ float warp_sum(float v) {
    #pragma unroll
    for (int o = 16; o; o >>= 1) v += __shfl_xor_sync(0xFFFFFFFFu, v, o);
    return v;
}
__device__ __forceinline__ float warp_max(float v) {
    #pragma unroll
    for (int o = 16; o; o >>= 1) v = fmaxf(v, __shfl_xor_sync(0xFFFFFFFFu, v, o));
    return v;
}

// ---------------------------------------------------------------------------
// K1: dec_feature[b,i] = sum_j dec_hidden[b,j] * W[i,j] + bias[i]
// one warp per (b,i); W row contiguous -> coalesced float4 loads
// ---------------------------------------------------------------------------
__global__ void k_decfeat(const float* __restrict__ dh,
                          const float* __restrict__ W,
                          const float* __restrict__ bias,
                          float* __restrict__ out) {
    int warp = (blockIdx.x * blockDim.x + threadIdx.x) >> 5;
    int lane = threadIdx.x & 31;
    if (warp >= B_ * D_) return;
    int b = warp >> 10;          // / D_
    int i = warp & (D_ - 1);
    const float4* wrow = (const float4*)(W + (size_t)i * D_);
    const float4* x    = (const float4*)(dh + (size_t)b * D_);
    float acc = 0.f;
    #pragma unroll
    for (int k = 0; k < 8; k++) {
        float4 wv = wrow[lane + k * 32];
        float4 xv = x[lane + k * 32];
        acc += wv.x * xv.x + wv.y * xv.y + wv.z * xv.z + wv.w * xv.w;
    }
    acc = warp_sum(acc);
    if (lane == 0) out[warp] = acc + bias[i];
}

// ---------------------------------------------------------------------------
// K2: score[b,l] = sum_d tanh(enc_feature[b,l,d] + dec_feature[b,d]
//                              + coverage[b,l]*w_cov[d]) * w_score[d]
// one warp per (b,l); streams enc_feature (256 MB) once
// ---------------------------------------------------------------------------
__global__ void k_score(const float* __restrict__ ef,
                        const float* __restrict__ cov,
                        const float* __restrict__ wcov,
                        const float* __restrict__ wscore,
                        const float* __restrict__ decf,
                        float* __restrict__ score) {
    int warp = (blockIdx.x * blockDim.x + threadIdx.x) >> 5;
    int lane = threadIdx.x & 31;
    if (warp >= B_ * L_) return;
    int b = warp >> 12;          // / L_
    const float4* e  = (const float4*)(ef + (size_t)warp * D_);
    const float4* df = (const float4*)(decf + (size_t)b * D_);
    const float4* wc = (const float4*)wcov;
    const float4* ws = (const float4*)wscore;
    float c = cov[warp];
    float acc = 0.f;
    #pragma unroll
    for (int k = 0; k < 8; k++) {
        int idx = lane + k * 32;
        float4 ev = e[idx];
        float4 dv = df[idx];
        float4 cv = wc[idx];
        float4 sv = ws[idx];
        acc += tanh_approx(fmaf(c, cv.x, ev.x + dv.x)) * sv.x;
        acc += tanh_approx(fmaf(c, cv.y, ev.y + dv.y)) * sv.y;
        acc += tanh_approx(fmaf(c, cv.z, ev.z + dv.z)) * sv.z;
        acc += tanh_approx(fmaf(c, cv.w, ev.w + dv.w)) * sv.w;
    }
    acc = warp_sum(acc);
    if (lane == 0) score[warp] = acc;
}

// ---------------------------------------------------------------------------
// K3: per-batch masked softmax + renormalize (denominators cancel ->
//     attn_i = e^{s_i-max} * m_i / sum_j e^{s_j-max} * m_j),
//     new_coverage = attn + coverage, and zero the context region.
// one block (1024 threads) per batch
// ---------------------------------------------------------------------------
__global__ void k_softmax(const float* __restrict__ score,
                          const float* __restrict__ mask,
                          const float* __restrict__ cov,
                          float* __restrict__ attn,
                          float* __restrict__ newcov,
                          float* __restrict__ context) {
    int b = blockIdx.x;
    int t = threadIdx.x;               // 0..1023
    __shared__ float red[32];
    const float* sc = score + (size_t)b * L_;
    const float* mk = mask  + (size_t)b * L_;
    const float* cv = cov   + (size_t)b * L_;

    float s[4];
    float mx = -CUDART_INF_F;
    #pragma unroll
    for (int j = 0; j < 4; j++) {
        s[j] = sc[t + j * 1024];
        mx = fmaxf(mx, s[j]);
    }
    // block max
    mx = warp_max(mx);
    if ((t & 31) == 0) red[t >> 5] = mx;
    __syncthreads();
    if (t < 32) {
        float v = red[t];
        v = warp_max(v);
        red[t] = v;
    }
    __syncthreads();
    mx = red[0];

    float e[4];
    float sum = 0.f;
    #pragma unroll
    for (int j = 0; j < 4; j++) {
        e[j] = __expf(s[j] - mx) * mk[t + j * 1024];
        sum += e[j];
    }
    __syncthreads();
    sum = warp_sum(sum);
    if ((t & 31) == 0) red[t >> 5] = sum;
    __syncthreads();
    if (t < 32) {
        float v = red[t];
        v = warp_sum(v);
        red[t] = v;
    }
    __syncthreads();
    float inv = 1.f / red[0];

    #pragma unroll
    for (int j = 0; j < 4; j++) {
        int idx = t + j * 1024;
        float a = e[j] * inv;
        attn[(size_t)b * L_ + idx]   = a;
        newcov[(size_t)b * L_ + idx] = a + cv[idx];
    }
    // zero context[b, :] (D_ == blockDim)
    context[(size_t)b * D_ + t] = 0.f;
}

// ---------------------------------------------------------------------------
// K4: context[b,d] = sum_l attn[b,l] * enc_output[b,l,d]
// block = 256 threads, each owns a float4 -> covers the full D=1024 row.
// grid (lchunk=64, b=16); each block accumulates 64 rows; LDG.128 streaming.
// ---------------------------------------------------------------------------
#define LCHUNK 64
__global__ void __launch_bounds__(256) k_context(
        const float* __restrict__ attn,
        const float* __restrict__ enc,
        float* __restrict__ context) {
    int b = blockIdx.y;
    int lchunk = blockIdx.x;
    int t = threadIdx.x;               // 0..255

    __shared__ float a[LCHUNK];
    if (t < LCHUNK) a[t] = attn[(size_t)b * L_ + lchunk * LCHUNK + t];
    __syncthreads();

    // row base: enc[b, lchunk*LCHUNK, 0], thread t covers floats [4t, 4t+4)
    const float4* base = (const float4*)(enc
                          + ((size_t)b * L_ + (size_t)lchunk * LCHUNK) * D_) + t;
    float4 acc = make_float4(0.f, 0.f, 0.f, 0.f);
    #pragma unroll 8
    for (int l = 0; l < LCHUNK; l++) {
        float4 v = base[(size_t)l * (D_ / 4)];
        float w = a[l];
        acc.x = fmaf(w, v.x, acc.x);
        acc.y = fmaf(w, v.y, acc.y);
        acc.z = fmaf(w, v.z, acc.z);
        acc.w = fmaf(w, v.w, acc.w);
    }
    float* dst = context + (size_t)b * D_ + t * 4;
    atomicAdd(dst + 0, acc.x);
    atomicAdd(dst + 1, acc.y);
    atomicAdd(dst + 2, acc.z);
    atomicAdd(dst + 3, acc.w);
}

// ---------------------------------------------------------------------------
extern "C" void kernel_launch(void* const* d_in, const int* in_sizes, int n_in,
                              void* d_out, int out_size) {
    const float* dec_hidden  = (const float*)d_in[0];  // [16,1024]
    const float* enc_output  = (const float*)d_in[1];  // [16,4096,1024]
    const float* enc_feature = (const float*)d_in[2];  // [16,4096,1024]
    const float* enc_mask    = (const float*)d_in[3];  // [16,4096]
    // d_in[4] = sec_attn -- dead code in the reference, unused
    const float* coverage    = (const float*)d_in[5];  // [16,4096]
    const float* W_feat      = (const float*)d_in[6];  // [1024,1024]
    const float* b_feat      = (const float*)d_in[7];  // [1024]
    const float* w_score     = (const float*)d_in[8];  // [1024]
    const float* w_cov       = (const float*)d_in[9];  // [1024]

    float* out = (float*)d_out;
    float* attn_out   = out;                     // [16,4096]
    float* context    = out + B_ * L_;           // [16,1024]
    float* newcov_out = out + B_ * L_ + B_ * D_; // [16,4096]

    float* decf;  cudaGetSymbolAddress((void**)&decf,  g_decfeat);
    float* score; cudaGetSymbolAddress((void**)&score, g_score);

    // K1: dec_feature GEMV — 16384 warps, 256 thr/block
    k_decfeat<<<(B_ * D_ * 32) / 256, 256>>>(dec_hidden, W_feat, b_feat, decf);

    // K2: scores — 65536 warps, 256 thr/block
    k_score<<<(B_ * L_ * 32) / 256, 256>>>(enc_feature, coverage, w_cov,
                                           w_score, decf, score);

    // K3: softmax + mask + renorm + new_coverage + zero context
    k_softmax<<<B_, 1024>>>(score, enc_mask, coverage,
                            attn_out, newcov_out, context);

    // K4: weighted context accumulation — 1024 blocks
    dim3 g4(L_ / LCHUNK, B_);
    k_context<<<g4, 256>>>(attn_out, enc_output, context);
}

// round 7
// speedup vs baseline: 1.1803x; 1.1803x over previous
#include <cuda_runtime.h>
#include <cuda_bf16.h>
#include <math_constants.h>

// Shapes
#define B_  16
#define L_  4096
#define D_  1024

// Scratch (allocation-free rule: __device__ globals)
__device__ float g_decfeat[B_ * D_];   // dec_hidden @ W^T + b
__device__ float g_score[B_ * L_];     // pre-softmax scores

__device__ __forceinline__ float tanh_approx(float x) {
    float y;
    asm("tanh.approx.f32 %0, %1;" : "=f"(y) : "f"(x));
    return y;
}

__device__ __forceinline__ float warp_sum(float v) {
    #pragma unroll
    for (int o = 16; o; o >>= 1) v += __shfl_xor_sync(0xFFFFFFFFu, v, o);
    return v;
}
__device__ __forceinline__ float warp_max(float v) {
    #pragma unroll
    for (int o = 16; o; o >>= 1) v = fmaxf(v, __shfl_xor_sync(0xFFFFFFFFu, v, o));
    return v;
}

// ---------------------------------------------------------------------------
// K1: dec_feature[b,i] = sum_j dec_hidden[b,j] * W[i,j] + bias[i]
// one warp per (b,i); W row contiguous -> coalesced float4 loads
// ---------------------------------------------------------------------------
__global__ void k_decfeat(const float* __restrict__ dh,
                          const float* __restrict__ W,
                          const float* __restrict__ bias,
                          float* __restrict__ out) {
    int warp = (blockIdx.x * blockDim.x + threadIdx.x) >> 5;
    int lane = threadIdx.x & 31;
    if (warp >= B_ * D_) return;
    int b = warp >> 10;          // / D_
    int i = warp & (D_ - 1);
    const float4* wrow = (const float4*)(W + (size_t)i * D_);
    const float4* x    = (const float4*)(dh + (size_t)b * D_);
    float acc = 0.f;
    #pragma unroll
    for (int k = 0; k < 8; k++) {
        float4 wv = wrow[lane + k * 32];
        float4 xv = x[lane + k * 32];
        acc += wv.x * xv.x + wv.y * xv.y + wv.z * xv.z + wv.w * xv.w;
    }
    acc = warp_sum(acc);
    if (lane == 0) out[warp] = acc + bias[i];
}

// ---------------------------------------------------------------------------
// K2: score[b,l] = sum_d tanh(enc_feature[b,l,d] + dec_feature[b,d]
//                              + coverage[b,l]*w_cov[d]) * w_score[d]
// one warp per (b,l); streams enc_feature (256 MB) once -> __ldcs evict-first
// ---------------------------------------------------------------------------
__global__ void k_score(const float* __restrict__ ef,
                        const float* __restrict__ cov,
                        const float* __restrict__ wcov,
                        const float* __restrict__ wscore,
                        const float* __restrict__ decf,
                        float* __restrict__ score) {
    int warp = (blockIdx.x * blockDim.x + threadIdx.x) >> 5;
    int lane = threadIdx.x & 31;
    if (warp >= B_ * L_) return;
    int b = warp >> 12;          // / L_
    const float4* e  = (const float4*)(ef + (size_t)warp * D_);
    const float4* df = (const float4*)(decf + (size_t)b * D_);
    const float4* wc = (const float4*)wcov;
    const float4* ws = (const float4*)wscore;
    float c = cov[warp];
    float acc = 0.f;
    #pragma unroll
    for (int k = 0; k < 8; k++) {
        int idx = lane + k * 32;
        float4 ev = __ldcs(e + idx);   // streaming: read-once tensor
        float4 dv = df[idx];
        float4 cv = wc[idx];
        float4 sv = ws[idx];
        acc += tanh_approx(fmaf(c, cv.x, ev.x + dv.x)) * sv.x;
        acc += tanh_approx(fmaf(c, cv.y, ev.y + dv.y)) * sv.y;
        acc += tanh_approx(fmaf(c, cv.z, ev.z + dv.z)) * sv.z;
        acc += tanh_approx(fmaf(c, cv.w, ev.w + dv.w)) * sv.w;
    }
    acc = warp_sum(acc);
    if (lane == 0) score[warp] = acc;
}

// ---------------------------------------------------------------------------
// K3: per-batch masked softmax + renormalize (denominators cancel ->
//     attn_i = e^{s_i-max} * m_i / sum_j e^{s_j-max} * m_j),
//     new_coverage = attn + coverage, and zero the context region.
// one block (1024 threads) per batch
// ---------------------------------------------------------------------------
__global__ void k_softmax(const float* __restrict__ score,
                          const float* __restrict__ mask,
                          const float* __restrict__ cov,
                          float* __restrict__ attn,
                          float* __restrict__ newcov,
                          float* __restrict__ context) {
    int b = blockIdx.x;
    int t = threadIdx.x;               // 0..1023
    __shared__ float red[32];
    const float* sc = score + (size_t)b * L_;
    const float* mk = mask  + (size_t)b * L_;
    const float* cv = cov   + (size_t)b * L_;

    float s[4];
    float mx = -CUDART_INF_F;
    #pragma unroll
    for (int j = 0; j < 4; j++) {
        s[j] = sc[t + j * 1024];
        mx = fmaxf(mx, s[j]);
    }
    // block max
    mx = warp_max(mx);
    if ((t & 31) == 0) red[t >> 5] = mx;
    __syncthreads();
    if (t < 32) {
        float v = red[t];
        v = warp_max(v);
        red[t] = v;
    }
    __syncthreads();
    mx = red[0];

    float e[4];
    float sum = 0.f;
    #pragma unroll
    for (int j = 0; j < 4; j++) {
        e[j] = __expf(s[j] - mx) * mk[t + j * 1024];
        sum += e[j];
    }
    __syncthreads();
    sum = warp_sum(sum);
    if ((t & 31) == 0) red[t >> 5] = sum;
    __syncthreads();
    if (t < 32) {
        float v = red[t];
        v = warp_sum(v);
        red[t] = v;
    }
    __syncthreads();
    float inv = 1.f / red[0];

    #pragma unroll
    for (int j = 0; j < 4; j++) {
        int idx = t + j * 1024;
        float a = e[j] * inv;
        attn[(size_t)b * L_ + idx]   = a;
        newcov[(size_t)b * L_ + idx] = a + cv[idx];
    }
    // zero context[b, :] (D_ == blockDim)
    context[(size_t)b * D_ + t] = 0.f;
}

// ---------------------------------------------------------------------------
// K4: context[b,d] = sum_l attn[b,l] * enc_output[b,l,d]
// grid (lchunk=32, dchunk=8, b=16); block 128 threads; split-L atomics
// (reverted to Round-4 measured-best config; + __ldcs on the stream)
// ---------------------------------------------------------------------------
__global__ void k_context(const float* __restrict__ attn,
                          const float* __restrict__ enc,
                          float* __restrict__ context) {
    int b = blockIdx.z;
    int dchunk = blockIdx.y;
    int lchunk = blockIdx.x;
    int t = threadIdx.x;               // 0..127

    __shared__ float a[128];
    a[t] = attn[(size_t)b * L_ + lchunk * 128 + t];
    __syncthreads();

    const float* base = enc + ((size_t)b * L_ + (size_t)lchunk * 128) * D_
                            + dchunk * 128 + t;
    float acc = 0.f;
    #pragma unroll 8
    for (int l = 0; l < 128; l++) {
        acc = fmaf(a[l], __ldcs(base + (size_t)l * D_), acc);
    }
    atomicAdd(&context[(size_t)b * D_ + dchunk * 128 + t], acc);
}

// ---------------------------------------------------------------------------
extern "C" void kernel_launch(void* const* d_in, const int* in_sizes, int n_in,
                              void* d_out, int out_size) {
    const float* dec_hidden  = (const float*)d_in[0];  // [16,1024]
    const float* enc_output  = (const float*)d_in[1];  // [16,4096,1024]
    const float* enc_feature = (const float*)d_in[2];  // [16,4096,1024]
    const float* enc_mask    = (const float*)d_in[3];  // [16,4096]
    // d_in[4] = sec_attn -- dead code in the reference, unused
    const float* coverage    = (const float*)d_in[5];  // [16,4096]
    const float* W_feat      = (const float*)d_in[6];  // [1024,1024]
    const float* b_feat      = (const float*)d_in[7];  // [1024]
    const float* w_score     = (const float*)d_in[8];  // [1024]
    const float* w_cov       = (const float*)d_in[9];  // [1024]

    float* out = (float*)d_out;
    float* attn_out   = out;                     // [16,4096]
    float* context    = out + B_ * L_;           // [16,1024]
    float* newcov_out = out + B_ * L_ + B_ * D_; // [16,4096]

    float* decf;  cudaGetSymbolAddress((void**)&decf,  g_decfeat);
    float* score; cudaGetSymbolAddress((void**)&score, g_score);

    // K1: dec_feature GEMV — 16384 warps, 256 thr/block
    k_decfeat<<<(B_ * D_ * 32) / 256, 256>>>(dec_hidden, W_feat, b_feat, decf);

    // K2: scores — 65536 warps, 256 thr/block
    k_score<<<(B_ * L_ * 32) / 256, 256>>>(enc_feature, coverage, w_cov,
                                           w_score, decf, score);

    // K3: softmax + mask + renorm + new_coverage + zero context
    k_softmax<<<B_, 1024>>>(score, enc_mask, coverage,
                            attn_out, newcov_out, context);

    // K4: weighted context accumulation
    dim3 g4(L_ / 128, D_ / 128, B_);
    k_context<<<g4, 128>>>(attn_out, enc_output, context);
}